// round 1
// baseline (speedup 1.0000x reference)
#include <cuda_runtime.h>
#include <math_constants.h>

#define F 256
#define CHUNK 128
#define NW 8        // warps per block (256 threads)
#define RPB 8       // rows per block in the small output GEMM
#define MAX_SEGS 4096

// Scratch (no cudaMalloc allowed): pooled rows + per-segment softmax stats.
__device__ float g_pooled[MAX_SEGS * F];
__device__ float g_seg_max[MAX_SEGS];
__device__ float g_seg_inv[MAX_SEGS];

__device__ __forceinline__ int lower_bound_dev(const int* __restrict__ a, int n, int key) {
    int lo = 0, hi = n;
    while (lo < hi) {
        int mid = (lo + hi) >> 1;
        if (a[mid] < key) lo = mid + 1; else hi = mid;
    }
    return lo;
}

// ---------------------------------------------------------------------------
// Kernel 1: one block per segment. Online-softmax fused gate + weighted pool.
//   Phase (a): warp-per-row dot(x_row, W_gate) -> logits (smem + global stash)
//   Phase (b): chunk max -> rescale running acc/denom; w = exp(l - m_new)
//   Phase (c): thread-per-column acc += w[i] * x[row_i][col]  (chunk re-read
//              hits L2: 512 blocks * 128KB = 64MB < L2)
// ---------------------------------------------------------------------------
__global__ void __launch_bounds__(256) seg_pool_kernel(
    const float* __restrict__ x,
    const int*   __restrict__ batch,
    const float* __restrict__ Wg,
    float*       __restrict__ gate_buf,   // [n] — stash logits here, finalized later
    int n_nodes)
{
    __shared__ float lg_s[CHUNK];
    __shared__ float w_s[CHUNK];
    __shared__ float red[NW];
    __shared__ float bc0;
    __shared__ float d_sm;

    const int tid  = threadIdx.x;
    const int wid  = tid >> 5;
    const int lane = tid & 31;
    const int s    = blockIdx.x;

    const int start = lower_bound_dev(batch, n_nodes, s);
    const int end   = lower_bound_dev(batch, n_nodes, s + 1);

    if (tid == 0) d_sm = 0.0f;
    __syncthreads();

    // W_gate in registers per lane: elements [lane*4..+3] and [128+lane*4..+3]
    const float4 wgA = ((const float4*)Wg)[lane];
    const float4 wgB = ((const float4*)Wg)[lane + 32];

    float acc   = 0.0f;       // per-thread: column `tid` of the pooled sum (unnormalized)
    float m_run = -CUDART_INF_F;

    for (int base = start; base < end; base += CHUNK) {
        const int cnt = min(CHUNK, end - base);

        // ---- (a) logits: warp per row ----
        for (int i = wid; i < cnt; i += NW) {
            const float4* xr = (const float4*)(x + (size_t)(base + i) * F);
            float4 a = xr[lane];
            float4 b = xr[lane + 32];
            float p = a.x*wgA.x + a.y*wgA.y + a.z*wgA.z + a.w*wgA.w
                    + b.x*wgB.x + b.y*wgB.y + b.z*wgB.z + b.w*wgB.w;
            #pragma unroll
            for (int off = 16; off; off >>= 1)
                p += __shfl_down_sync(0xffffffffu, p, off);
            if (lane == 0) { lg_s[i] = p; gate_buf[base + i] = p; }
        }
        __syncthreads();

        // ---- (b) chunk max ----
        float lm = -CUDART_INF_F;
        for (int i = tid; i < cnt; i += 256) lm = fmaxf(lm, lg_s[i]);
        #pragma unroll
        for (int off = 16; off; off >>= 1)
            lm = fmaxf(lm, __shfl_down_sync(0xffffffffu, lm, off));
        if (lane == 0) red[wid] = lm;
        __syncthreads();
        if (wid == 0) {
            float v = (lane < NW) ? red[lane] : -CUDART_INF_F;
            #pragma unroll
            for (int off = 4; off; off >>= 1)
                v = fmaxf(v, __shfl_down_sync(0xffffffffu, v, off));
            if (lane == 0) bc0 = v;
        }
        __syncthreads();

        const float m_new = fmaxf(m_run, bc0);
        const float scale = expf(m_run - m_new);   // 0 when m_run == -inf
        acc *= scale;

        // weights + local sum
        float ls = 0.0f;
        for (int i = tid; i < cnt; i += 256) {
            float w = expf(lg_s[i] - m_new);
            w_s[i] = w;
            ls += w;
        }
        #pragma unroll
        for (int off = 16; off; off >>= 1)
            ls += __shfl_down_sync(0xffffffffu, ls, off);
        if (lane == 0) red[wid] = ls;
        __syncthreads();
        if (tid == 0) {
            float sum = 0.0f;
            #pragma unroll
            for (int w2 = 0; w2 < NW; w2++) sum += red[w2];
            d_sm = d_sm * scale + sum;
        }
        __syncthreads();

        // ---- (c) weighted accumulate, thread = column ----
        const float* xp = x + (size_t)base * F + tid;
        int i = 0;
        for (; i + 8 <= cnt; i += 8) {
            float x0 = xp[(i + 0) * F];
            float x1 = xp[(i + 1) * F];
            float x2 = xp[(i + 2) * F];
            float x3 = xp[(i + 3) * F];
            float x4 = xp[(i + 4) * F];
            float x5 = xp[(i + 5) * F];
            float x6 = xp[(i + 6) * F];
            float x7 = xp[(i + 7) * F];
            acc += w_s[i + 0] * x0;
            acc += w_s[i + 1] * x1;
            acc += w_s[i + 2] * x2;
            acc += w_s[i + 3] * x3;
            acc += w_s[i + 4] * x4;
            acc += w_s[i + 5] * x5;
            acc += w_s[i + 6] * x6;
            acc += w_s[i + 7] * x7;
        }
        for (; i < cnt; i++) acc += w_s[i] * xp[i * F];

        m_run = m_new;
        __syncthreads();   // protect lg_s / w_s before next chunk
    }

    const float inv = 1.0f / (d_sm + 1e-16f);
    g_pooled[(size_t)s * F + tid] = acc * inv;
    if (tid == 0) { g_seg_max[s] = m_run; g_seg_inv[s] = inv; }
}

// ---------------------------------------------------------------------------
// Kernel 2: finalize gate output in place: gate[i] = exp(logit - m_s) * inv_s
// ---------------------------------------------------------------------------
__global__ void gate_final_kernel(float* __restrict__ gate_buf,
                                  const int* __restrict__ batch, int n)
{
    int i = blockIdx.x * blockDim.x + threadIdx.x;
    if (i < n) {
        int s = batch[i];
        gate_buf[i] = expf(gate_buf[i] - g_seg_max[s]) * g_seg_inv[s];
    }
}

// ---------------------------------------------------------------------------
// Kernel 3: out = pooled @ W_nn + b_nn   ([S,256] @ [256,256], tiny)
// ---------------------------------------------------------------------------
__global__ void __launch_bounds__(256) out_gemm_kernel(
    const float* __restrict__ Wnn,
    const float* __restrict__ bnn,     // may be null
    float*       __restrict__ out,
    int S)
{
    __shared__ float p_s[RPB][F];
    const int tid = threadIdx.x;
    const int r0  = blockIdx.x * RPB;

    #pragma unroll
    for (int r = 0; r < RPB; r++) {
        int s = r0 + r;
        p_s[r][tid] = (s < S) ? g_pooled[(size_t)s * F + tid] : 0.0f;
    }
    __syncthreads();

    float b = bnn ? bnn[tid] : 0.0f;
    float accv[RPB];
    #pragma unroll
    for (int r = 0; r < RPB; r++) accv[r] = b;

    for (int k = 0; k < F; k++) {
        float wv = Wnn[k * F + tid];
        #pragma unroll
        for (int r = 0; r < RPB; r++) accv[r] += p_s[r][k] * wv;
    }

    #pragma unroll
    for (int r = 0; r < RPB; r++) {
        int s = r0 + r;
        if (s < S) out[(size_t)s * F + tid] = accv[r];
    }
}

// ---------------------------------------------------------------------------
// Launch
// ---------------------------------------------------------------------------
extern "C" void kernel_launch(void* const* d_in, const int* in_sizes, int n_in,
                              void* d_out, int out_size)
{
    // Identify inputs by size/order:
    //   x = largest; batch = 2nd largest; W_nn = 3rd largest (65536);
    //   the two 256-element inputs are W_gate (first) then b_nn (second).
    //   b_gate (size 1) is a softmax-invariant shift -> ignored. "size" scalar ignored.
    int x_i = 0;
    for (int i = 1; i < n_in; i++) if (in_sizes[i] > in_sizes[x_i]) x_i = i;
    int b_i = -1;
    for (int i = 0; i < n_in; i++)
        if (i != x_i && (b_i < 0 || in_sizes[i] > in_sizes[b_i])) b_i = i;
    int wnn_i = -1;
    for (int i = 0; i < n_in; i++)
        if (i != x_i && i != b_i && (wnn_i < 0 || in_sizes[i] > in_sizes[wnn_i])) wnn_i = i;
    int wg_i = -1, bnn_i = -1;
    for (int i = 0; i < n_in; i++) {
        if (i == x_i || i == b_i || i == wnn_i) continue;
        if (in_sizes[i] == F) { if (wg_i < 0) wg_i = i; else bnn_i = i; }
    }

    const float* x     = (const float*)d_in[x_i];
    const int*   batch = (const int*)  d_in[b_i];
    const float* Wg    = (const float*)d_in[wg_i];
    const float* Wnn   = (const float*)d_in[wnn_i];
    const float* bnn   = (bnn_i >= 0) ? (const float*)d_in[bnn_i] : nullptr;

    const int n = in_sizes[b_i];                 // number of nodes
    int S;
    float* out  = (float*)d_out;
    float* gate;
    if (out_size > n && ((out_size - n) % F) == 0) {
        // Tuple layout: [out (S*F) | gate (n)]
        S    = (out_size - n) / F;
        gate = out + (size_t)S * F;
    } else {
        // Fallback: out only; still need a gate buffer for logits/weights.
        S    = out_size / F;
        static_assert(MAX_SEGS * F >= 0, "");
        gate = g_pooled;  // unused fallback path (won't occur for this problem)
    }
    if (S > MAX_SEGS) S = MAX_SEGS;

    seg_pool_kernel<<<S, 256>>>(x, batch, Wg, gate, n);
    gate_final_kernel<<<(n + 255) / 256, 256>>>(gate, batch, n);
    out_gemm_kernel<<<(S + RPB - 1) / RPB, 256>>>(Wnn, bnn, out, S);
}

// round 2
// speedup vs baseline: 1.0816x; 1.0816x over previous
#include <cuda_runtime.h>

#define F 256
#define NW 8          // warps per block
#define NT 256        // threads per block
#define SPLIT 4       // blocks per segment
#define RPB 8         // rows per block in output GEMM
#define MAX_SEGS 4096

// Scratch (no cudaMalloc allowed)
__device__ float g_pooled[MAX_SEGS * F];   // unnormalized weighted sums
__device__ float g_denom[MAX_SEGS];        // sum of exp(logit) per segment

__device__ __forceinline__ int lower_bound_dev(const int* __restrict__ a, int n, int key) {
    int lo = 0, hi = n;
    while (lo < hi) {
        int mid = (lo + hi) >> 1;
        if (a[mid] < key) lo = mid + 1; else hi = mid;
    }
    return lo;
}

// ---------------------------------------------------------------------------
// Kernel 0: zero the per-segment partial buffers (graph replays need this).
// ---------------------------------------------------------------------------
__global__ void init_kernel(int S) {
    int i = blockIdx.x * blockDim.x + threadIdx.x;
    if (i < S * F) g_pooled[i] = 0.0f;
    if (i < S)     g_denom[i] = 0.0f;
}

// ---------------------------------------------------------------------------
// Kernel 1: warp-per-row fused gate + weighted pool, single DRAM pass over x.
//   Each warp: load row (8 floats/lane), logit via bfly reduce from the SAME
//   registers, w = expf(logit), acc += w * row. No barriers in the main loop.
//   Block = (segment, slice): grid = S * SPLIT.
// ---------------------------------------------------------------------------
__global__ void __launch_bounds__(NT) seg_pool_kernel(
    const float* __restrict__ x,
    const int*   __restrict__ batch,
    const float* __restrict__ Wg,
    float*       __restrict__ gate_buf,   // [n] — stash w = exp(logit)
    int n_nodes)
{
    const int tid  = threadIdx.x;
    const int wid  = tid >> 5;
    const int lane = tid & 31;
    const int s     = blockIdx.x / SPLIT;
    const int slice = blockIdx.x % SPLIT;

    const int start = lower_bound_dev(batch, n_nodes, s);
    const int end   = lower_bound_dev(batch, n_nodes, s + 1);
    const int len   = end - start;
    const int a     = start + (int)(((long long)len * slice) / SPLIT);
    const int b     = start + (int)(((long long)len * (slice + 1)) / SPLIT);

    // W_gate per lane: cols [4*lane..+3] and [128+4*lane..+3]
    const float4 wgA = ((const float4*)Wg)[lane];
    const float4 wgB = ((const float4*)Wg)[lane + 32];

    float4 accA = make_float4(0.f, 0.f, 0.f, 0.f);
    float4 accB = make_float4(0.f, 0.f, 0.f, 0.f);
    float  dsum = 0.0f;

    int row = a + wid;
    float4 cA, cB;
    if (row < b) {
        const float4* xr = (const float4*)(x + (size_t)row * F);
        cA = xr[lane];
        cB = xr[lane + 32];
    }
    while (row < b) {
        const int nxt = row + NW;
        float4 nA, nB;
        if (nxt < b) {                       // prefetch next row (hides DRAM latency)
            const float4* xr = (const float4*)(x + (size_t)nxt * F);
            nA = xr[lane];
            nB = xr[lane + 32];
        }

        float p = cA.x*wgA.x + cA.y*wgA.y + cA.z*wgA.z + cA.w*wgA.w
                + cB.x*wgB.x + cB.y*wgB.y + cB.z*wgB.z + cB.w*wgB.w;
        #pragma unroll
        for (int off = 16; off; off >>= 1)
            p += __shfl_xor_sync(0xffffffffu, p, off);   // all lanes get the sum

        const float w = __expf(p);
        if (lane == 0) gate_buf[row] = w;
        dsum += w;

        accA.x += w * cA.x;  accA.y += w * cA.y;  accA.z += w * cA.z;  accA.w += w * cA.w;
        accB.x += w * cB.x;  accB.y += w * cB.y;  accB.z += w * cB.z;  accB.w += w * cB.w;

        row = nxt;
        cA = nA; cB = nB;
    }

    // ---- block reduce (once per block) ----
    __shared__ float acc_s[NW][F];
    __shared__ float d_s[NW];

    *((float4*)&acc_s[wid][4 * lane])       = accA;
    *((float4*)&acc_s[wid][128 + 4 * lane]) = accB;
    if (lane == 0) d_s[wid] = dsum;
    __syncthreads();

    float v = 0.0f;
    #pragma unroll
    for (int w2 = 0; w2 < NW; w2++) v += acc_s[w2][tid];
    atomicAdd(&g_pooled[(size_t)s * F + tid], v);

    if (tid == 0) {
        float dd = 0.0f;
        #pragma unroll
        for (int w2 = 0; w2 < NW; w2++) dd += d_s[w2];
        atomicAdd(&g_denom[s], dd);
    }
}

// ---------------------------------------------------------------------------
// Kernel 2: gate[i] = w_i / (denom[s] + 1e-16)
// ---------------------------------------------------------------------------
__global__ void gate_final_kernel(float* __restrict__ gate_buf,
                                  const int* __restrict__ batch, int n)
{
    int i = blockIdx.x * blockDim.x + threadIdx.x;
    if (i < n) {
        int s = batch[i];
        gate_buf[i] = gate_buf[i] / (g_denom[s] + 1e-16f);
    }
}

// ---------------------------------------------------------------------------
// Kernel 3: out = (pooled * inv) @ W_nn + (denom*inv) * b_nn
//   (bias coefficient = sum of gates = denom/(denom+eps): exact for empty segs)
// ---------------------------------------------------------------------------
__global__ void __launch_bounds__(NT) out_gemm_kernel(
    const float* __restrict__ Wnn,
    const float* __restrict__ bnn,     // may be null
    float*       __restrict__ out,
    int S)
{
    __shared__ float p_s[RPB][F];
    __shared__ float gsc[RPB];
    const int tid = threadIdx.x;
    const int r0  = blockIdx.x * RPB;

    #pragma unroll
    for (int r = 0; r < RPB; r++) {
        int s = r0 + r;
        if (s < S) {
            float d   = g_denom[s];
            float inv = 1.0f / (d + 1e-16f);
            p_s[r][tid] = g_pooled[(size_t)s * F + tid] * inv;
            if (tid == 0) gsc[r] = d * inv;
        } else {
            p_s[r][tid] = 0.0f;
            if (tid == 0) gsc[r] = 0.0f;
        }
    }
    __syncthreads();

    const float bv = bnn ? bnn[tid] : 0.0f;
    float accv[RPB];
    #pragma unroll
    for (int r = 0; r < RPB; r++) accv[r] = gsc[r] * bv;

    for (int k = 0; k < F; k++) {
        float wv = Wnn[k * F + tid];
        #pragma unroll
        for (int r = 0; r < RPB; r++) accv[r] += p_s[r][k] * wv;
    }

    #pragma unroll
    for (int r = 0; r < RPB; r++) {
        int s = r0 + r;
        if (s < S) out[(size_t)s * F + tid] = accv[r];
    }
}

// ---------------------------------------------------------------------------
// Launch
// ---------------------------------------------------------------------------
extern "C" void kernel_launch(void* const* d_in, const int* in_sizes, int n_in,
                              void* d_out, int out_size)
{
    // Identify inputs by size: x = largest; batch = 2nd; W_nn = 3rd (65536);
    // the two 256-element tensors are W_gate (first) then b_nn (second).
    // b_gate (size 1) shifts logits uniformly -> softmax-invariant -> ignored.
    int x_i = 0;
    for (int i = 1; i < n_in; i++) if (in_sizes[i] > in_sizes[x_i]) x_i = i;
    int b_i = -1;
    for (int i = 0; i < n_in; i++)
        if (i != x_i && (b_i < 0 || in_sizes[i] > in_sizes[b_i])) b_i = i;
    int wnn_i = -1;
    for (int i = 0; i < n_in; i++)
        if (i != x_i && i != b_i && (wnn_i < 0 || in_sizes[i] > in_sizes[wnn_i])) wnn_i = i;
    int wg_i = -1, bnn_i = -1;
    for (int i = 0; i < n_in; i++) {
        if (i == x_i || i == b_i || i == wnn_i) continue;
        if (in_sizes[i] == F) { if (wg_i < 0) wg_i = i; else bnn_i = i; }
    }

    const float* x     = (const float*)d_in[x_i];
    const int*   batch = (const int*)  d_in[b_i];
    const float* Wg    = (const float*)d_in[wg_i];
    const float* Wnn   = (const float*)d_in[wnn_i];
    const float* bnn   = (bnn_i >= 0) ? (const float*)d_in[bnn_i] : nullptr;

    const int n = in_sizes[b_i];
    int S;
    float* out  = (float*)d_out;
    float* gate;
    if (out_size > n && ((out_size - n) % F) == 0) {
        S    = (out_size - n) / F;         // tuple layout: [out (S*F) | gate (n)]
        gate = out + (size_t)S * F;
    } else {
        S    = out_size / F;
        gate = out;                        // fallback (not expected for this problem)
    }
    if (S > MAX_SEGS) S = MAX_SEGS;

    init_kernel<<<(S * F + NT - 1) / NT, NT>>>(S);
    seg_pool_kernel<<<S * SPLIT, NT>>>(x, batch, Wg, gate, n);
    gate_final_kernel<<<(n + NT - 1) / NT, NT>>>(gate, batch, n);
    out_gemm_kernel<<<(S + RPB - 1) / RPB, NT>>>(Wnn, bnn, out, S);
}

// round 4
// speedup vs baseline: 1.5009x; 1.3876x over previous
#include <cuda_runtime.h>

#define F 256
#define NW 8          // warps per block
#define NT 256        // threads per block
#define SPLIT 4       // blocks per segment in seg_pool
#define RPB 8         // rows per block in output GEMM
#define KCH 64        // k-chunk per block in output GEMM
#define MAX_SEGS 4096

// Scratch (no cudaMalloc allowed)
__device__ float g_pooled[MAX_SEGS * F];   // unnormalized weighted sums
__device__ float g_denom[MAX_SEGS];        // sum of exp(logit) per segment

__device__ __forceinline__ int lower_bound_dev(const int* __restrict__ a, int n, int key) {
    int lo = 0, hi = n;
    while (lo < hi) {
        int mid = (lo + hi) >> 1;
        if (a[mid] < key) lo = mid + 1; else hi = mid;
    }
    return lo;
}

// ---------------------------------------------------------------------------
// Kernel 0: zero per-segment partials AND the out region (graph replays
// accumulate atomics, so out must be re-zeroed every replay).
// ---------------------------------------------------------------------------
__global__ void init_kernel(float* __restrict__ out, int S) {
    int i = blockIdx.x * blockDim.x + threadIdx.x;
    if (i < S * F) { g_pooled[i] = 0.0f; out[i] = 0.0f; }
    if (i < S)     g_denom[i] = 0.0f;
}

// ---------------------------------------------------------------------------
// Kernel 1: warp-per-row fused gate + weighted pool, single DRAM pass over x.
//   Each warp: load row (8 floats/lane), logit via bfly reduce from the SAME
//   registers, w = expf(logit), acc += w * row. No barriers in the main loop.
// ---------------------------------------------------------------------------
__global__ void __launch_bounds__(NT) seg_pool_kernel(
    const float* __restrict__ x,
    const int*   __restrict__ batch,
    const float* __restrict__ Wg,
    float*       __restrict__ gate_buf,   // [n] — stash w = exp(logit)
    int n_nodes)
{
    const int tid  = threadIdx.x;
    const int wid  = tid >> 5;
    const int lane = tid & 31;
    const int s     = blockIdx.x / SPLIT;
    const int slice = blockIdx.x % SPLIT;

    const int start = lower_bound_dev(batch, n_nodes, s);
    const int end   = lower_bound_dev(batch, n_nodes, s + 1);
    const int len   = end - start;
    const int a     = start + (int)(((long long)len * slice) / SPLIT);
    const int b     = start + (int)(((long long)len * (slice + 1)) / SPLIT);

    const float4 wgA = ((const float4*)Wg)[lane];
    const float4 wgB = ((const float4*)Wg)[lane + 32];

    float4 accA = make_float4(0.f, 0.f, 0.f, 0.f);
    float4 accB = make_float4(0.f, 0.f, 0.f, 0.f);
    float  dsum = 0.0f;

    int row = a + wid;
    float4 cA, cB;
    if (row < b) {
        const float4* xr = (const float4*)(x + (size_t)row * F);
        cA = xr[lane];
        cB = xr[lane + 32];
    }
    while (row < b) {
        const int nxt = row + NW;
        float4 nA, nB;
        if (nxt < b) {                       // prefetch next row (hides DRAM latency)
            const float4* xr = (const float4*)(x + (size_t)nxt * F);
            nA = xr[lane];
            nB = xr[lane + 32];
        }

        float p = cA.x*wgA.x + cA.y*wgA.y + cA.z*wgA.z + cA.w*wgA.w
                + cB.x*wgB.x + cB.y*wgB.y + cB.z*wgB.z + cB.w*wgB.w;
        #pragma unroll
        for (int off = 16; off; off >>= 1)
            p += __shfl_xor_sync(0xffffffffu, p, off);   // all lanes get the sum

        const float w = __expf(p);
        if (lane == 0) gate_buf[row] = w;
        dsum += w;

        accA.x += w * cA.x;  accA.y += w * cA.y;  accA.z += w * cA.z;  accA.w += w * cA.w;
        accB.x += w * cB.x;  accB.y += w * cB.y;  accB.z += w * cB.z;  accB.w += w * cB.w;

        row = nxt;
        cA = nA; cB = nB;
    }

    __shared__ float acc_s[NW][F];
    __shared__ float d_s[NW];

    *((float4*)&acc_s[wid][4 * lane])       = accA;
    *((float4*)&acc_s[wid][128 + 4 * lane]) = accB;
    if (lane == 0) d_s[wid] = dsum;
    __syncthreads();

    float v = 0.0f;
    #pragma unroll
    for (int w2 = 0; w2 < NW; w2++) v += acc_s[w2][tid];
    atomicAdd(&g_pooled[(size_t)s * F + tid], v);

    if (tid == 0) {
        float dd = 0.0f;
        #pragma unroll
        for (int w2 = 0; w2 < NW; w2++) dd += d_s[w2];
        atomicAdd(&g_denom[s], dd);
    }
}

// ---------------------------------------------------------------------------
// Kernel 2: gate[i] = w_i / (denom[s] + 1e-16)
// ---------------------------------------------------------------------------
__global__ void gate_final_kernel(float* __restrict__ gate_buf,
                                  const int* __restrict__ batch, int n)
{
    int i = blockIdx.x * blockDim.x + threadIdx.x;
    if (i < n) {
        int s = batch[i];
        gate_buf[i] = gate_buf[i] / (g_denom[s] + 1e-16f);
    }
}

// ---------------------------------------------------------------------------
// Kernel 3: out += (pooled_norm chunk) @ (Wnn chunk)   — split-K GEMM.
//   grid = (ceil(S/RPB), F/KCH). Block (bx,ky): rows [bx*RPB, +RPB),
//   k in [ky*KCH, +KCH). p chunk staged (normalized) in smem; k-loop
//   unrolled x4 with 4 independent Wnn loads in flight; atomicAdd to out.
//   ky==0 blocks also add the bias term gsc*b_nn  (gsc = d/(d+eps)).
// ---------------------------------------------------------------------------
__global__ void __launch_bounds__(NT) out_gemm_kernel(
    const float* __restrict__ Wnn,
    const float* __restrict__ bnn,     // may be null
    float*       __restrict__ out,
    int S)
{
    __shared__ float p_s[RPB][KCH];
    __shared__ float gsc[RPB];

    const int tid = threadIdx.x;
    const int r0  = blockIdx.x * RPB;
    const int k0  = blockIdx.y * KCH;

    // Stage normalized p chunk: RPB*KCH = 512 elements, 2 per thread.
    #pragma unroll
    for (int e = tid; e < RPB * KCH; e += NT) {
        int r = e / KCH, k = e % KCH;
        int s = r0 + r;
        float v = 0.0f;
        if (s < S) {
            float d = g_denom[s];
            v = g_pooled[(size_t)s * F + (k0 + k)] / (d + 1e-16f);
        }
        p_s[r][k] = v;
    }
    if (tid < RPB) {
        int s = r0 + tid;
        float d = (s < S) ? g_denom[s] : 0.0f;
        gsc[tid] = d / (d + 1e-16f);
    }
    __syncthreads();

    float accv[RPB];
    if (blockIdx.y == 0 && bnn) {
        const float bv = bnn[tid];
        #pragma unroll
        for (int r = 0; r < RPB; r++) accv[r] = gsc[r] * bv;
    } else {
        #pragma unroll
        for (int r = 0; r < RPB; r++) accv[r] = 0.0f;
    }

    const float* Wp = Wnn + (size_t)k0 * F + tid;
    #pragma unroll
    for (int kk = 0; kk < KCH; kk += 4) {
        // 4 independent global loads (coalesced across threads, L2-resident)
        float w0 = Wp[(size_t)(kk + 0) * F];
        float w1 = Wp[(size_t)(kk + 1) * F];
        float w2 = Wp[(size_t)(kk + 2) * F];
        float w3 = Wp[(size_t)(kk + 3) * F];
        #pragma unroll
        for (int r = 0; r < RPB; r++) {
            float4 p4 = *(const float4*)&p_s[r][kk];   // smem broadcast
            accv[r] += p4.x * w0;
            accv[r] += p4.y * w1;
            accv[r] += p4.z * w2;
            accv[r] += p4.w * w3;
        }
    }

    #pragma unroll
    for (int r = 0; r < RPB; r++) {
        int s = r0 + r;
        if (s < S) atomicAdd(&out[(size_t)s * F + tid], accv[r]);
    }
}

// ---------------------------------------------------------------------------
// Launch
// ---------------------------------------------------------------------------
extern "C" void kernel_launch(void* const* d_in, const int* in_sizes, int n_in,
                              void* d_out, int out_size)
{
    // Identify inputs by size: x = largest; batch = 2nd; W_nn = 3rd (65536);
    // the two 256-element tensors are W_gate (first) then b_nn (second).
    // b_gate (size 1) shifts logits uniformly -> softmax-invariant -> ignored.
    int x_i = 0;
    for (int i = 1; i < n_in; i++) if (in_sizes[i] > in_sizes[x_i]) x_i = i;
    int b_i = -1;
    for (int i = 0; i < n_in; i++)
        if (i != x_i && (b_i < 0 || in_sizes[i] > in_sizes[b_i])) b_i = i;
    int wnn_i = -1;
    for (int i = 0; i < n_in; i++)
        if (i != x_i && i != b_i && (wnn_i < 0 || in_sizes[i] > in_sizes[wnn_i])) wnn_i = i;
    int wg_i = -1, bnn_i = -1;
    for (int i = 0; i < n_in; i++) {
        if (i == x_i || i == b_i || i == wnn_i) continue;
        if (in_sizes[i] == F) { if (wg_i < 0) wg_i = i; else bnn_i = i; }
    }

    const float* x     = (const float*)d_in[x_i];
    const int*   batch = (const int*)  d_in[b_i];
    const float* Wg    = (const float*)d_in[wg_i];
    const float* Wnn   = (const float*)d_in[wnn_i];
    const float* bnn   = (bnn_i >= 0) ? (const float*)d_in[bnn_i] : nullptr;

    const int n = in_sizes[b_i];
    int S;
    float* out  = (float*)d_out;
    float* gate;
    if (out_size > n && ((out_size - n) % F) == 0) {
        S    = (out_size - n) / F;         // tuple layout: [out (S*F) | gate (n)]
        gate = out + (size_t)S * F;
    } else {
        S    = out_size / F;
        gate = out;                        // fallback (not expected for this problem)
    }
    if (S > MAX_SEGS) S = MAX_SEGS;

    init_kernel<<<(S * F + NT - 1) / NT, NT>>>(out, S);
    seg_pool_kernel<<<S * SPLIT, NT>>>(x, batch, Wg, gate, n);
    gate_final_kernel<<<(n + NT - 1) / NT, NT>>>(gate, batch, n);
    dim3 gg((S + RPB - 1) / RPB, F / KCH);
    out_gemm_kernel<<<gg, NT>>>(Wnn, bnn, out, S);
}

// round 8
// speedup vs baseline: 1.6554x; 1.1030x over previous
#include <cuda_runtime.h>

#define F 256
#define NW 8          // warps per block
#define NT 256        // threads per block
#define SPLIT 4       // blocks per segment in seg_pool
#define RPB 8         // rows per block in output GEMM
#define KCH 32        // k-chunk per block in output GEMM
#define MAX_SEGS 4096

// Scratch (no cudaMalloc allowed)
__device__ float g_pooled[MAX_SEGS * F];   // unnormalized weighted sums
__device__ float g_denom[MAX_SEGS];        // sum of exp(logit) per segment

__device__ __forceinline__ int lower_bound_dev(const int* __restrict__ a, int n, int key) {
    int lo = 0, hi = n;
    while (lo < hi) {
        int mid = (lo + hi) >> 1;
        if (a[mid] < key) lo = mid + 1; else hi = mid;
    }
    return lo;
}

// ---------------------------------------------------------------------------
// Kernel 0: zero per-segment partials AND the out region (graph replays
// accumulate atomics, so out must be re-zeroed every replay).
// ---------------------------------------------------------------------------
__global__ void init_kernel(float* __restrict__ out, int S) {
    int i = blockIdx.x * blockDim.x + threadIdx.x;
    if (i < S * F) { g_pooled[i] = 0.0f; out[i] = 0.0f; }
    if (i < S)     g_denom[i] = 0.0f;
}

// ---------------------------------------------------------------------------
// Kernel 1: fused gate + weighted pool, single DRAM pass over x.
//   Each warp processes TWO rows per iteration (independent dot/reduce/exp
//   chains -> ILP 2) and prefetches the next two (16 LDG.128 in flight).
//   NOTE: redux.sync.add.f32 is rejected by ptxas on the harness's
//   compute_100 PTX target — use interleaved shuffle butterflies instead.
// ---------------------------------------------------------------------------
__global__ void __launch_bounds__(NT) seg_pool_kernel(
    const float* __restrict__ x,
    const int*   __restrict__ batch,
    const float* __restrict__ Wg,
    float*       __restrict__ gate_buf,   // [n] — stash w = exp(logit)
    int n_nodes)
{
    const int tid  = threadIdx.x;
    const int wid  = tid >> 5;
    const int lane = tid & 31;
    const int s     = blockIdx.x / SPLIT;
    const int slice = blockIdx.x % SPLIT;

    const int start = lower_bound_dev(batch, n_nodes, s);
    const int end   = lower_bound_dev(batch, n_nodes, s + 1);
    const int len   = end - start;
    const int a     = start + (int)(((long long)len * slice) / SPLIT);
    const int b     = start + (int)(((long long)len * (slice + 1)) / SPLIT);

    const float4 wgA = ((const float4*)Wg)[lane];
    const float4 wgB = ((const float4*)Wg)[lane + 32];

    float4 accA = make_float4(0.f, 0.f, 0.f, 0.f);
    float4 accB = make_float4(0.f, 0.f, 0.f, 0.f);
    float  dsum = 0.0f;

    // Row pair for this warp: (r, r+NW); stride 2*NW per iteration.
    int r0 = a + wid;
    float4 c0A, c0B, c1A, c1B;
    if (r0 < b) {
        const float4* xr = (const float4*)(x + (size_t)r0 * F);
        c0A = xr[lane]; c0B = xr[lane + 32];
    }
    if (r0 + NW < b) {
        const float4* xr = (const float4*)(x + (size_t)(r0 + NW) * F);
        c1A = xr[lane]; c1B = xr[lane + 32];
    }

    while (r0 < b) {
        const int p0 = r0 + 2 * NW;
        const int p1 = r0 + 3 * NW;
        float4 n0A, n0B, n1A, n1B;
        if (p0 < b) {
            const float4* xr = (const float4*)(x + (size_t)p0 * F);
            n0A = xr[lane]; n0B = xr[lane + 32];
        }
        if (p1 < b) {
            const float4* xr = (const float4*)(x + (size_t)p1 * F);
            n1A = xr[lane]; n1B = xr[lane + 32];
        }

        // Two independent dot products (ILP across the shuffle chains)
        float q0 = c0A.x*wgA.x + c0A.y*wgA.y + c0A.z*wgA.z + c0A.w*wgA.w
                 + c0B.x*wgB.x + c0B.y*wgB.y + c0B.z*wgB.z + c0B.w*wgB.w;
        float q1 = c1A.x*wgA.x + c1A.y*wgA.y + c1A.z*wgA.z + c1A.w*wgA.w
                 + c1B.x*wgB.x + c1B.y*wgB.y + c1B.z*wgB.z + c1B.w*wgB.w;

        // Interleave the two butterflies explicitly so they pipeline.
        #pragma unroll
        for (int off = 16; off; off >>= 1) {
            q0 += __shfl_xor_sync(0xffffffffu, q0, off);
            q1 += __shfl_xor_sync(0xffffffffu, q1, off);
        }
        const float w0 = __expf(q0);
        const float w1 = __expf(q1);

        // row r0 is always valid inside the loop
        if (lane == 0) gate_buf[r0] = w0;
        dsum += w0;
        accA.x += w0 * c0A.x;  accA.y += w0 * c0A.y;  accA.z += w0 * c0A.z;  accA.w += w0 * c0A.w;
        accB.x += w0 * c0B.x;  accB.y += w0 * c0B.y;  accB.z += w0 * c0B.z;  accB.w += w0 * c0B.w;

        if (r0 + NW < b) {
            if (lane == 0) gate_buf[r0 + NW] = w1;
            dsum += w1;
            accA.x += w1 * c1A.x;  accA.y += w1 * c1A.y;  accA.z += w1 * c1A.z;  accA.w += w1 * c1A.w;
            accB.x += w1 * c1B.x;  accB.y += w1 * c1B.y;  accB.z += w1 * c1B.z;  accB.w += w1 * c1B.w;
        }

        r0 = p0;
        c0A = n0A; c0B = n0B; c1A = n1A; c1B = n1B;
    }

    // ---- block reduce (once per block) ----
    __shared__ float acc_s[NW][F];
    __shared__ float d_s[NW];

    *((float4*)&acc_s[wid][4 * lane])       = accA;
    *((float4*)&acc_s[wid][128 + 4 * lane]) = accB;
    if (lane == 0) d_s[wid] = dsum;
    __syncthreads();

    float v = 0.0f;
    #pragma unroll
    for (int w2 = 0; w2 < NW; w2++) v += acc_s[w2][tid];
    atomicAdd(&g_pooled[(size_t)s * F + tid], v);

    if (tid == 0) {
        float dd = 0.0f;
        #pragma unroll
        for (int w2 = 0; w2 < NW; w2++) dd += d_s[w2];
        atomicAdd(&g_denom[s], dd);
    }
}

// ---------------------------------------------------------------------------
// Kernel 2: gate[i] = w_i / (denom[s] + 1e-16)
// ---------------------------------------------------------------------------
__global__ void gate_final_kernel(float* __restrict__ gate_buf,
                                  const int* __restrict__ batch, int n)
{
    int i = blockIdx.x * blockDim.x + threadIdx.x;
    if (i < n) {
        int s = batch[i];
        gate_buf[i] = gate_buf[i] / (g_denom[s] + 1e-16f);
    }
}

// ---------------------------------------------------------------------------
// Kernel 3: out += (pooled_norm chunk) @ (Wnn chunk)   — split-K GEMM.
//   grid = (ceil(S/RPB), F/KCH) = 512 blocks. Software-pipelined Wnn loads:
//   next 4 loads issued before FMAs on current 4, so the LSU queue never
//   drains. atomicAdd partials to out; ky==0 adds bias gsc*b_nn.
// ---------------------------------------------------------------------------
__global__ void __launch_bounds__(NT) out_gemm_kernel(
    const float* __restrict__ Wnn,
    const float* __restrict__ bnn,     // may be null
    float*       __restrict__ out,
    int S)
{
    __shared__ float p_s[RPB][KCH];
    __shared__ float gsc[RPB];

    const int tid = threadIdx.x;
    const int r0  = blockIdx.x * RPB;
    const int k0  = blockIdx.y * KCH;

    // Stage normalized p chunk: RPB*KCH = 256 elements, 1 per thread.
    {
        int r = tid / KCH, k = tid % KCH;
        int s = r0 + r;
        float v = 0.0f;
        if (s < S) {
            float d = g_denom[s];
            v = g_pooled[(size_t)s * F + (k0 + k)] / (d + 1e-16f);
        }
        p_s[r][k] = v;
    }
    if (tid < RPB) {
        int s = r0 + tid;
        float d = (s < S) ? g_denom[s] : 0.0f;
        gsc[tid] = d / (d + 1e-16f);
    }
    __syncthreads();

    float accv[RPB];
    if (blockIdx.y == 0 && bnn) {
        const float bv = bnn[tid];
        #pragma unroll
        for (int r = 0; r < RPB; r++) accv[r] = gsc[r] * bv;
    } else {
        #pragma unroll
        for (int r = 0; r < RPB; r++) accv[r] = 0.0f;
    }

    const float* Wp = Wnn + (size_t)k0 * F + tid;

    // Preload first 4 W values, then pipeline: issue next 4 loads, FMA current 4.
    float w0 = Wp[0 * F];
    float w1 = Wp[1 * F];
    float w2 = Wp[2 * F];
    float w3 = Wp[3 * F];

    #pragma unroll
    for (int kk = 0; kk < KCH; kk += 4) {
        float v0 = 0.f, v1 = 0.f, v2 = 0.f, v3 = 0.f;
        if (kk + 4 < KCH) {
            v0 = Wp[(size_t)(kk + 4) * F];
            v1 = Wp[(size_t)(kk + 5) * F];
            v2 = Wp[(size_t)(kk + 6) * F];
            v3 = Wp[(size_t)(kk + 7) * F];
        }
        #pragma unroll
        for (int r = 0; r < RPB; r++) {
            float4 p4 = *(const float4*)&p_s[r][kk];   // smem broadcast
            accv[r] += p4.x * w0;
            accv[r] += p4.y * w1;
            accv[r] += p4.z * w2;
            accv[r] += p4.w * w3;
        }
        w0 = v0; w1 = v1; w2 = v2; w3 = v3;
    }

    #pragma unroll
    for (int r = 0; r < RPB; r++) {
        int s = r0 + r;
        if (s < S) atomicAdd(&out[(size_t)s * F + tid], accv[r]);
    }
}

// ---------------------------------------------------------------------------
// Launch
// ---------------------------------------------------------------------------
extern "C" void kernel_launch(void* const* d_in, const int* in_sizes, int n_in,
                              void* d_out, int out_size)
{
    // Identify inputs by size: x = largest; batch = 2nd; W_nn = 3rd (65536);
    // the two 256-element tensors are W_gate (first) then b_nn (second).
    // b_gate (size 1) shifts logits uniformly -> softmax-invariant -> ignored.
    int x_i = 0;
    for (int i = 1; i < n_in; i++) if (in_sizes[i] > in_sizes[x_i]) x_i = i;
    int b_i = -1;
    for (int i = 0; i < n_in; i++)
        if (i != x_i && (b_i < 0 || in_sizes[i] > in_sizes[b_i])) b_i = i;
    int wnn_i = -1;
    for (int i = 0; i < n_in; i++)
        if (i != x_i && i != b_i && (wnn_i < 0 || in_sizes[i] > in_sizes[wnn_i])) wnn_i = i;
    int wg_i = -1, bnn_i = -1;
    for (int i = 0; i < n_in; i++) {
        if (i == x_i || i == b_i || i == wnn_i) continue;
        if (in_sizes[i] == F) { if (wg_i < 0) wg_i = i; else bnn_i = i; }
    }

    const float* x     = (const float*)d_in[x_i];
    const int*   batch = (const int*)  d_in[b_i];
    const float* Wg    = (const float*)d_in[wg_i];
    const float* Wnn   = (const float*)d_in[wnn_i];
    const float* bnn   = (bnn_i >= 0) ? (const float*)d_in[bnn_i] : nullptr;

    const int n = in_sizes[b_i];
    int S;
    float* out  = (float*)d_out;
    float* gate;
    if (out_size > n && ((out_size - n) % F) == 0) {
        S    = (out_size - n) / F;         // tuple layout: [out (S*F) | gate (n)]
        gate = out + (size_t)S * F;
    } else {
        S    = out_size / F;
        gate = out;                        // fallback (not expected for this problem)
    }
    if (S > MAX_SEGS) S = MAX_SEGS;

    init_kernel<<<(S * F + NT - 1) / NT, NT>>>(out, S);
    seg_pool_kernel<<<S * SPLIT, NT>>>(x, batch, Wg, gate, n);
    gate_final_kernel<<<(n + NT - 1) / NT, NT>>>(gate, batch, n);
    dim3 gg((S + RPB - 1) / RPB, F / KCH);
    out_gemm_kernel<<<gg, NT>>>(Wnn, bnn, out, S);
}

// round 9
// speedup vs baseline: 1.7630x; 1.0650x over previous
#include <cuda_runtime.h>
#include <cuda_pipeline.h>

#define F 256
#define NW 8          // warps per block
#define NT 256        // threads per block
#define SPLIT 4       // blocks per segment in seg_pool
#define DEPTH 4       // row slots per warp ring (cp.async lookahead)
#define RPB 8         // rows per block in output GEMM
#define KCH 32        // k-chunk per block in output GEMM
#define MAX_SEGS 4096

// Scratch (no cudaMalloc allowed)
__device__ float g_pooled[MAX_SEGS * F];   // unnormalized weighted sums
__device__ float g_denom[MAX_SEGS];        // sum of exp(logit) per segment

__device__ __forceinline__ int lower_bound_dev(const int* __restrict__ a, int n, int key) {
    int lo = 0, hi = n;
    while (lo < hi) {
        int mid = (lo + hi) >> 1;
        if (a[mid] < key) lo = mid + 1; else hi = mid;
    }
    return lo;
}

// ---------------------------------------------------------------------------
// Kernel 0: zero per-segment partials AND the out region (graph replays
// accumulate atomics, so out must be re-zeroed every replay).
// ---------------------------------------------------------------------------
__global__ void init_kernel(float* __restrict__ out, int S) {
    int i = blockIdx.x * blockDim.x + threadIdx.x;
    if (i < S * F) { g_pooled[i] = 0.0f; out[i] = 0.0f; }
    if (i < S)     g_denom[i] = 0.0f;
}

// ---------------------------------------------------------------------------
// Kernel 1: fused gate + weighted pool, single DRAM pass over x.
//   cp.async per-warp smem ring: DEPTH=4 rows (4KB) in flight per warp at
//   ZERO register cost. Each lane copies and later reads only its own 2x16B
//   segments of a row, so per-thread cp.async completion needs no syncwarp.
//   Two rows consumed per iteration (ILP-2 shuffle chains). No barriers in
//   the main loop. Ring smem is reused for the block reduction afterwards.
// ---------------------------------------------------------------------------
__global__ void __launch_bounds__(NT) seg_pool_kernel(
    const float* __restrict__ x,
    const int*   __restrict__ batch,
    const float* __restrict__ Wg,
    float*       __restrict__ gate_buf,   // [n] — stash w = exp(logit)
    int n_nodes)
{
    __shared__ __align__(16) float ring[NW][DEPTH][F];   // 32 KB
    __shared__ float d_s[NW];

    const int tid  = threadIdx.x;
    const int wid  = tid >> 5;
    const int lane = tid & 31;
    const int s     = blockIdx.x / SPLIT;
    const int slice = blockIdx.x % SPLIT;

    const int start = lower_bound_dev(batch, n_nodes, s);
    const int end   = lower_bound_dev(batch, n_nodes, s + 1);
    const int len   = end - start;
    const int a     = start + (int)(((long long)len * slice) / SPLIT);
    const int b     = start + (int)(((long long)len * (slice + 1)) / SPLIT);

    const float4 wgA = ((const float4*)Wg)[lane];
    const float4 wgB = ((const float4*)Wg)[lane + 32];

    float4 accA = make_float4(0.f, 0.f, 0.f, 0.f);
    float4 accB = make_float4(0.f, 0.f, 0.f, 0.f);
    float  dsum = 0.0f;

    const int o0 = 4 * lane;          // this lane's first float4 within a row
    const int o1 = 128 + 4 * lane;    // this lane's second float4

    // Prologue: issue DEPTH rows, one commit group per row (empty if invalid).
    #pragma unroll
    for (int d = 0; d < DEPTH; d++) {
        int r = a + wid + d * NW;
        if (r < b) {
            const float* rp = x + (size_t)r * F;
            __pipeline_memcpy_async(&ring[wid][d][o0], rp + o0, 16);
            __pipeline_memcpy_async(&ring[wid][d][o1], rp + o1, 16);
        }
        __pipeline_commit();
    }

    int r0 = a + wid;     // first row of the pair this iteration
    int j  = 0;           // row counter for slot indexing
    while (r0 < b) {
        const int r1    = r0 + NW;
        const int slot0 = j & (DEPTH - 1);
        const int slot1 = (j + 1) & (DEPTH - 1);

        // Oldest two groups (rows j, j+1) must be complete.
        __pipeline_wait_prior(2);

        float4 c0A = *(const float4*)&ring[wid][slot0][o0];
        float4 c0B = *(const float4*)&ring[wid][slot0][o1];
        float4 c1A = *(const float4*)&ring[wid][slot1][o0];  // garbage if r1>=b (guarded)
        float4 c1B = *(const float4*)&ring[wid][slot1][o1];

        // Two independent dot products
        float q0 = c0A.x*wgA.x + c0A.y*wgA.y + c0A.z*wgA.z + c0A.w*wgA.w
                 + c0B.x*wgB.x + c0B.y*wgB.y + c0B.z*wgB.z + c0B.w*wgB.w;
        float q1 = c1A.x*wgA.x + c1A.y*wgA.y + c1A.z*wgA.z + c1A.w*wgA.w
                 + c1B.x*wgB.x + c1B.y*wgB.y + c1B.z*wgB.z + c1B.w*wgB.w;

        // Interleaved butterflies (the two chains pipeline through SHFL unit)
        #pragma unroll
        for (int off = 16; off; off >>= 1) {
            q0 += __shfl_xor_sync(0xffffffffu, q0, off);
            q1 += __shfl_xor_sync(0xffffffffu, q1, off);
        }
        const float w0 = __expf(q0);
        const float w1 = __expf(q1);

        // Refill just-consumed slots with rows j+DEPTH, j+DEPTH+1.
        {
            int rn0 = r0 + DEPTH * NW;
            if (rn0 < b) {
                const float* rp = x + (size_t)rn0 * F;
                __pipeline_memcpy_async(&ring[wid][slot0][o0], rp + o0, 16);
                __pipeline_memcpy_async(&ring[wid][slot0][o1], rp + o1, 16);
            }
            __pipeline_commit();
            int rn1 = r1 + DEPTH * NW;
            if (rn1 < b) {
                const float* rp = x + (size_t)rn1 * F;
                __pipeline_memcpy_async(&ring[wid][slot1][o0], rp + o0, 16);
                __pipeline_memcpy_async(&ring[wid][slot1][o1], rp + o1, 16);
            }
            __pipeline_commit();
        }

        // Consume row r0 (always valid inside loop)
        if (lane == 0) gate_buf[r0] = w0;
        dsum += w0;
        accA.x += w0 * c0A.x;  accA.y += w0 * c0A.y;  accA.z += w0 * c0A.z;  accA.w += w0 * c0A.w;
        accB.x += w0 * c0B.x;  accB.y += w0 * c0B.y;  accB.z += w0 * c0B.z;  accB.w += w0 * c0B.w;

        if (r1 < b) {
            if (lane == 0) gate_buf[r1] = w1;
            dsum += w1;
            accA.x += w1 * c1A.x;  accA.y += w1 * c1A.y;  accA.z += w1 * c1A.z;  accA.w += w1 * c1A.w;
            accB.x += w1 * c1B.x;  accB.y += w1 * c1B.y;  accB.z += w1 * c1B.z;  accB.w += w1 * c1B.w;
        }

        r0 += 2 * NW;
        j  += 2;
    }

    // Drain all in-flight copies before reusing ring as the reduction buffer.
    __pipeline_wait_prior(0);
    __syncthreads();

    // ---- block reduce (reuse ring smem: [NW][F] fits in [NW][DEPTH][F]) ----
    float* acc_s = &ring[0][0][0];     // logical layout [NW][F]
    *((float4*)&acc_s[wid * F + 4 * lane])       = accA;
    *((float4*)&acc_s[wid * F + 128 + 4 * lane]) = accB;
    if (lane == 0) d_s[wid] = dsum;
    __syncthreads();

    float v = 0.0f;
    #pragma unroll
    for (int w2 = 0; w2 < NW; w2++) v += acc_s[w2 * F + tid];
    atomicAdd(&g_pooled[(size_t)s * F + tid], v);

    if (tid == 0) {
        float dd = 0.0f;
        #pragma unroll
        for (int w2 = 0; w2 < NW; w2++) dd += d_s[w2];
        atomicAdd(&g_denom[s], dd);
    }
}

// ---------------------------------------------------------------------------
// Kernel 2: gate[i] = w_i / (denom[s] + 1e-16)
// ---------------------------------------------------------------------------
__global__ void gate_final_kernel(float* __restrict__ gate_buf,
                                  const int* __restrict__ batch, int n)
{
    int i = blockIdx.x * blockDim.x + threadIdx.x;
    if (i < n) {
        int s = batch[i];
        gate_buf[i] = gate_buf[i] / (g_denom[s] + 1e-16f);
    }
}

// ---------------------------------------------------------------------------
// Kernel 3: out += (pooled_norm chunk) @ (Wnn chunk)   — split-K GEMM.
//   (unchanged from R8: 512 blocks, software-pipelined Wnn loads)
// ---------------------------------------------------------------------------
__global__ void __launch_bounds__(NT) out_gemm_kernel(
    const float* __restrict__ Wnn,
    const float* __restrict__ bnn,     // may be null
    float*       __restrict__ out,
    int S)
{
    __shared__ float p_s[RPB][KCH];
    __shared__ float gsc[RPB];

    const int tid = threadIdx.x;
    const int r0  = blockIdx.x * RPB;
    const int k0  = blockIdx.y * KCH;

    {
        int r = tid / KCH, k = tid % KCH;
        int s = r0 + r;
        float v = 0.0f;
        if (s < S) {
            float d = g_denom[s];
            v = g_pooled[(size_t)s * F + (k0 + k)] / (d + 1e-16f);
        }
        p_s[r][k] = v;
    }
    if (tid < RPB) {
        int s = r0 + tid;
        float d = (s < S) ? g_denom[s] : 0.0f;
        gsc[tid] = d / (d + 1e-16f);
    }
    __syncthreads();

    float accv[RPB];
    if (blockIdx.y == 0 && bnn) {
        const float bv = bnn[tid];
        #pragma unroll
        for (int r = 0; r < RPB; r++) accv[r] = gsc[r] * bv;
    } else {
        #pragma unroll
        for (int r = 0; r < RPB; r++) accv[r] = 0.0f;
    }

    const float* Wp = Wnn + (size_t)k0 * F + tid;

    float w0 = Wp[0 * F];
    float w1 = Wp[1 * F];
    float w2 = Wp[2 * F];
    float w3 = Wp[3 * F];

    #pragma unroll
    for (int kk = 0; kk < KCH; kk += 4) {
        float v0 = 0.f, v1 = 0.f, v2 = 0.f, v3 = 0.f;
        if (kk + 4 < KCH) {
            v0 = Wp[(size_t)(kk + 4) * F];
            v1 = Wp[(size_t)(kk + 5) * F];
            v2 = Wp[(size_t)(kk + 6) * F];
            v3 = Wp[(size_t)(kk + 7) * F];
        }
        #pragma unroll
        for (int r = 0; r < RPB; r++) {
            float4 p4 = *(const float4*)&p_s[r][kk];
            accv[r] += p4.x * w0;
            accv[r] += p4.y * w1;
            accv[r] += p4.z * w2;
            accv[r] += p4.w * w3;
        }
        w0 = v0; w1 = v1; w2 = v2; w3 = v3;
    }

    #pragma unroll
    for (int r = 0; r < RPB; r++) {
        int s = r0 + r;
        if (s < S) atomicAdd(&out[(size_t)s * F + tid], accv[r]);
    }
}

// ---------------------------------------------------------------------------
// Launch
// ---------------------------------------------------------------------------
extern "C" void kernel_launch(void* const* d_in, const int* in_sizes, int n_in,
                              void* d_out, int out_size)
{
    // Identify inputs by size: x = largest; batch = 2nd; W_nn = 3rd (65536);
    // the two 256-element tensors are W_gate (first) then b_nn (second).
    // b_gate (size 1) shifts logits uniformly -> softmax-invariant -> ignored.
    int x_i = 0;
    for (int i = 1; i < n_in; i++) if (in_sizes[i] > in_sizes[x_i]) x_i = i;
    int b_i = -1;
    for (int i = 0; i < n_in; i++)
        if (i != x_i && (b_i < 0 || in_sizes[i] > in_sizes[b_i])) b_i = i;
    int wnn_i = -1;
    for (int i = 0; i < n_in; i++)
        if (i != x_i && i != b_i && (wnn_i < 0 || in_sizes[i] > in_sizes[wnn_i])) wnn_i = i;
    int wg_i = -1, bnn_i = -1;
    for (int i = 0; i < n_in; i++) {
        if (i == x_i || i == b_i || i == wnn_i) continue;
        if (in_sizes[i] == F) { if (wg_i < 0) wg_i = i; else bnn_i = i; }
    }

    const float* x     = (const float*)d_in[x_i];
    const int*   batch = (const int*)  d_in[b_i];
    const float* Wg    = (const float*)d_in[wg_i];
    const float* Wnn   = (const float*)d_in[wnn_i];
    const float* bnn   = (bnn_i >= 0) ? (const float*)d_in[bnn_i] : nullptr;

    const int n = in_sizes[b_i];
    int S;
    float* out  = (float*)d_out;
    float* gate;
    if (out_size > n && ((out_size - n) % F) == 0) {
        S    = (out_size - n) / F;         // tuple layout: [out (S*F) | gate (n)]
        gate = out + (size_t)S * F;
    } else {
        S    = out_size / F;
        gate = out;                        // fallback (not expected for this problem)
    }
    if (S > MAX_SEGS) S = MAX_SEGS;

    init_kernel<<<(S * F + NT - 1) / NT, NT>>>(out, S);
    seg_pool_kernel<<<S * SPLIT, NT>>>(x, batch, Wg, gate, n);
    gate_final_kernel<<<(n + NT - 1) / NT, NT>>>(gate, batch, n);
    dim3 gg((S + RPB - 1) / RPB, F / KCH);
    out_gemm_kernel<<<gg, NT>>>(Wnn, bnn, out, S);
}